// round 2
// baseline (speedup 1.0000x reference)
#include <cuda_runtime.h>
#include <cstdint>
#include <cstddef>

// ---------------------------------------------------------------------------
// CTC-CRF logZ, bonito defaults: S=1024 states, NZ=5, N=32, T=2000.
//   alpha[t+1][s] = lse_z( Ms[t][s][z] + alpha[t][pred_z(s)] )
//   pred_0(s)=s, pred_{1+r}(s)=s//4+256r
// Strategy: forward scan over t<Tf and backward scan over t>=Tf run in
// parallel (grid 32 x 2); logZ = lse_s(alpha_mid + beta_mid).
// Exp2-domain recurrence with block renormalization every 8 steps.
// ---------------------------------------------------------------------------

#define NB   32
#define SS   1024
#define CC   5120
#define TPB  256
#define L2E  1.44269504088896f
#define LN2  0.69314718055995f

// smem layout (floats): [0,20480) 4 score stages; [20480,24576) work
// (fwd: alpha double buffer 2x1024; bwd: 4 c-planes of 1024); [24576,+16) red.
#define WOFF   20480
#define REDOFF (WOFF + 4096)
#define SMEM_F (REDOFF + 16)
#define SMEM_B (SMEM_F * 4)

__device__ __align__(16) float g_mid_a[NB][SS];
__device__ __align__(16) float g_mid_b[NB][SS];
__device__ float g_off[2][NB];

__device__ __forceinline__ float ex2f_(float x) {
    float r; asm("ex2.approx.f32 %0,%1;" : "=f"(r) : "f"(x)); return r;
}
__device__ __forceinline__ float lg2f_(float x) {
    float r; asm("lg2.approx.f32 %0,%1;" : "=f"(r) : "f"(x)); return r;
}
__device__ __forceinline__ float rcpf_(float x) {
    float r; asm("rcp.approx.f32 %0,%1;" : "=f"(r) : "f"(x)); return r;
}

__device__ __forceinline__ void cp_slab(const float* g, float* s, int tid) {
    uint32_t dst = (uint32_t)__cvta_generic_to_shared(s) + (uint32_t)tid * 16u;
    const char* src = (const char*)g + (size_t)tid * 16;
#pragma unroll
    for (int k = 0; k < 5; k++)
        asm volatile("cp.async.cg.shared.global [%0],[%1],16;"
                     :: "r"(dst + (uint32_t)k * 4096u), "l"(src + (size_t)k * 4096)
                     : "memory");
}
__device__ __forceinline__ void cp_commit() {
    asm volatile("cp.async.commit_group;" ::: "memory");
}
__device__ __forceinline__ void cp_wait2() {
    asm volatile("cp.async.wait_group 2;" ::: "memory");
}

__device__ __forceinline__ float wmaxf_(float m) {
#pragma unroll
    for (int o = 16; o; o >>= 1)
        m = fmaxf(m, __shfl_xor_sync(0xffffffffu, m, o));
    return m;
}

__global__ void __launch_bounds__(TPB, 1)
crf_scan(const float* __restrict__ sc, int T, int Tf) {
    extern __shared__ float sm[];
    const int tid  = threadIdx.x;
    const int n    = blockIdx.x;
    const int dir  = blockIdx.y;          // 0 = forward, 1 = backward
    const int wid  = tid >> 5;
    const int lane = tid & 31;
    float* red = sm + REDOFF;
    const int steps = dir ? (T - Tf) : Tf;

    // prologue: stages 0..2 in flight
#pragma unroll
    for (int p = 0; p < 3; p++) {
        if (p < steps) {
            int t = dir ? (T - 1 - p) : p;
            cp_slab(sc + ((size_t)t * NB + n) * CC, sm + (p & 3) * CC, tid);
        }
        cp_commit();
    }

    float off = 0.0f;

    if (dir == 0) {
        // ------------------------- FORWARD -------------------------
        // thread owns states s = 4*tid + m; move preds = tid + 256r (shared).
        float a0 = 1.f, a1 = 1.f, a2 = 1.f, a3 = 1.f;
        float* al = sm + WOFF;                       // alpha double buffer
        ((float4*)al)[tid] = make_float4(1.f, 1.f, 1.f, 1.f);

        for (int i = 0; i < steps; i++) {
            cp_wait2();
            __syncthreads();
            if (i + 3 < steps) {
                int t = i + 3;
                cp_slab(sc + ((size_t)t * NB + n) * CC, sm + ((i + 3) & 3) * CC, tid);
            }
            cp_commit();

            const float4* sp = (const float4*)(sm + (i & 3) * CC) + 5 * tid;
            float4 q0 = sp[0], q1 = sp[1], q2 = sp[2], q3 = sp[3], q4 = sp[4];

            const float* ac = al + (i & 1) * SS;
            float g0 = ac[tid], g1 = ac[tid + 256], g2 = ac[tid + 512], g3 = ac[tid + 768];

            if ((i & 7) == 0 && i) {                 // apply renorm from step i-1
                float mv = red[0];
#pragma unroll
                for (int k = 1; k < 8; k++) mv = fmaxf(mv, red[k]);
                float s = rcpf_(mv);
                off += lg2f_(mv);
                a0 *= s; a1 *= s; a2 *= s; a3 *= s;
                g0 *= s; g1 *= s; g2 *= s; g3 *= s;
            }

            float w0  = ex2f_(q0.x * L2E), w1  = ex2f_(q0.y * L2E);
            float w2  = ex2f_(q0.z * L2E), w3  = ex2f_(q0.w * L2E);
            float w4  = ex2f_(q1.x * L2E), w5  = ex2f_(q1.y * L2E);
            float w6  = ex2f_(q1.z * L2E), w7  = ex2f_(q1.w * L2E);
            float w8  = ex2f_(q2.x * L2E), w9  = ex2f_(q2.y * L2E);
            float w10 = ex2f_(q2.z * L2E), w11 = ex2f_(q2.w * L2E);
            float w12 = ex2f_(q3.x * L2E), w13 = ex2f_(q3.y * L2E);
            float w14 = ex2f_(q3.z * L2E), w15 = ex2f_(q3.w * L2E);
            float w16 = ex2f_(q4.x * L2E), w17 = ex2f_(q4.y * L2E);
            float w18 = ex2f_(q4.z * L2E), w19 = ex2f_(q4.w * L2E);

            float n0 = fmaf(w1,  g0, w0  * a0);
            n0 = fmaf(w2,  g1, n0); n0 = fmaf(w3,  g2, n0); n0 = fmaf(w4,  g3, n0);
            float n1 = fmaf(w6,  g0, w5  * a1);
            n1 = fmaf(w7,  g1, n1); n1 = fmaf(w8,  g2, n1); n1 = fmaf(w9,  g3, n1);
            float n2 = fmaf(w11, g0, w10 * a2);
            n2 = fmaf(w12, g1, n2); n2 = fmaf(w13, g2, n2); n2 = fmaf(w14, g3, n2);
            float n3 = fmaf(w16, g0, w15 * a3);
            n3 = fmaf(w17, g1, n3); n3 = fmaf(w18, g2, n3); n3 = fmaf(w19, g3, n3);

            a0 = n0; a1 = n1; a2 = n2; a3 = n3;
            ((float4*)(al + ((i + 1) & 1) * SS))[tid] = make_float4(n0, n1, n2, n3);

            if ((i & 7) == 7) {
                float m = wmaxf_(fmaxf(fmaxf(n0, n1), fmaxf(n2, n3)));
                if (lane == 0) red[wid] = m;
            }
        }

        // final renorm + publish
        {
            float m = wmaxf_(fmaxf(fmaxf(a0, a1), fmaxf(a2, a3)));
            if (lane == 0) red[wid] = m;
            __syncthreads();
            float mv = red[0];
#pragma unroll
            for (int k = 1; k < 8; k++) mv = fmaxf(mv, red[k]);
            float s = rcpf_(mv);
            off += lg2f_(mv);
            ((float4*)g_mid_a[n])[tid] = make_float4(a0 * s, a1 * s, a2 * s, a3 * s);
            if (tid == 0) g_off[0][n] = off;
        }
    } else {
        // ------------------------- BACKWARD -------------------------
        // beta[t][j] = lse( Ms[t][j][0]+beta'[j],
        //                   Ms[t][4*(j%256)+m'][1+j/256]+beta'[4*(j%256)+m'] )
        // Owner of s computes c[s][z]=w[s][z]*b'[s], scatters into z-planes
        // (group swizzle pi(g)=g^((g>>3)&7)); then gathers 4 contiguous states.
        float b0 = 1.f, b1 = 1.f, b2 = 1.f, b3 = 1.f;
        float* cpl = sm + WOFF;                      // 4 planes x 1024 floats
        const int pg  = tid ^ ((tid >> 3) & 7);      // scatter group
        const int r   = tid >> 6;                    // plane for gather
        const int gb  = 4 * (tid & 63);
        const int gp0 = (gb + 0) ^ (((gb + 0) >> 3) & 7);
        const int gp1 = (gb + 1) ^ (((gb + 1) >> 3) & 7);
        const int gp2 = (gb + 2) ^ (((gb + 2) >> 3) & 7);
        const int gp3 = (gb + 3) ^ (((gb + 3) >> 3) & 7);
        const float4* plane_r = (const float4*)(cpl + r * SS);

        for (int i = 0; i < steps; i++) {
            cp_wait2();
            __syncthreads();                         // (A) prev gather done; slab i ready
            if (i + 3 < steps) {
                int t = T - 1 - (i + 3);
                cp_slab(sc + ((size_t)t * NB + n) * CC, sm + ((i + 3) & 3) * CC, tid);
            }
            cp_commit();

            const float4* sp = (const float4*)(sm + (i & 3) * CC) + 5 * tid;
            float4 q0 = sp[0], q1 = sp[1], q2 = sp[2], q3 = sp[3], q4 = sp[4];

            if ((i & 7) == 0 && i) {
                float mv = red[0];
#pragma unroll
                for (int k = 1; k < 8; k++) mv = fmaxf(mv, red[k]);
                float s = rcpf_(mv);
                off += lg2f_(mv);
                b0 *= s; b1 *= s; b2 *= s; b3 *= s;
            }

            float w0  = ex2f_(q0.x * L2E), w1  = ex2f_(q0.y * L2E);
            float w2  = ex2f_(q0.z * L2E), w3  = ex2f_(q0.w * L2E);
            float w4  = ex2f_(q1.x * L2E), w5  = ex2f_(q1.y * L2E);
            float w6  = ex2f_(q1.z * L2E), w7  = ex2f_(q1.w * L2E);
            float w8  = ex2f_(q2.x * L2E), w9  = ex2f_(q2.y * L2E);
            float w10 = ex2f_(q2.z * L2E), w11 = ex2f_(q2.w * L2E);
            float w12 = ex2f_(q3.x * L2E), w13 = ex2f_(q3.y * L2E);
            float w14 = ex2f_(q3.z * L2E), w15 = ex2f_(q3.w * L2E);
            float w16 = ex2f_(q4.x * L2E), w17 = ex2f_(q4.y * L2E);
            float w18 = ex2f_(q4.z * L2E), w19 = ex2f_(q4.w * L2E);

            // scatter products into z-planes (conflict-free via pg swizzle)
            ((float4*)(cpl + 0 * SS))[pg] = make_float4(w1 * b0, w6 * b1, w11 * b2, w16 * b3);
            ((float4*)(cpl + 1 * SS))[pg] = make_float4(w2 * b0, w7 * b1, w12 * b2, w17 * b3);
            ((float4*)(cpl + 2 * SS))[pg] = make_float4(w3 * b0, w8 * b1, w13 * b2, w18 * b3);
            ((float4*)(cpl + 3 * SS))[pg] = make_float4(w4 * b0, w9 * b1, w14 * b2, w19 * b3);
            __syncthreads();                         // (B) scatter -> gather

            float4 c0 = plane_r[gp0];
            float4 c1 = plane_r[gp1];
            float4 c2 = plane_r[gp2];
            float4 c3 = plane_r[gp3];

            float m0 = fmaf(w0,  b0, (c0.x + c0.y) + (c0.z + c0.w));
            float m1 = fmaf(w5,  b1, (c1.x + c1.y) + (c1.z + c1.w));
            float m2 = fmaf(w10, b2, (c2.x + c2.y) + (c2.z + c2.w));
            float m3 = fmaf(w15, b3, (c3.x + c3.y) + (c3.z + c3.w));
            b0 = m0; b1 = m1; b2 = m2; b3 = m3;

            if ((i & 7) == 7) {
                float m = wmaxf_(fmaxf(fmaxf(m0, m1), fmaxf(m2, m3)));
                if (lane == 0) red[wid] = m;
            }
        }

        // final renorm + publish
        {
            float m = wmaxf_(fmaxf(fmaxf(b0, b1), fmaxf(b2, b3)));
            if (lane == 0) red[wid] = m;
            __syncthreads();
            float mv = red[0];
#pragma unroll
            for (int k = 1; k < 8; k++) mv = fmaxf(mv, red[k]);
            float s = rcpf_(mv);
            off += lg2f_(mv);
            ((float4*)g_mid_b[n])[tid] = make_float4(b0 * s, b1 * s, b2 * s, b3 * s);
            if (tid == 0) g_off[1][n] = off;
        }
    }
}

__global__ void __launch_bounds__(TPB)
crf_combine(float* __restrict__ out) {
    __shared__ float par[8];
    const int n = blockIdx.x, tid = threadIdx.x;
    float4 a = ((const float4*)g_mid_a[n])[tid];
    float4 b = ((const float4*)g_mid_b[n])[tid];
    float s = a.x * b.x + a.y * b.y + a.z * b.z + a.w * b.w;
#pragma unroll
    for (int o = 16; o; o >>= 1) s += __shfl_xor_sync(0xffffffffu, s, o);
    if ((tid & 31) == 0) par[tid >> 5] = s;
    __syncthreads();
    if (tid == 0) {
        float t = par[0];
#pragma unroll
        for (int k = 1; k < 8; k++) t += par[k];
        out[n] = LN2 * (g_off[0][n] + g_off[1][n] + lg2f_(t));
    }
}

extern "C" void kernel_launch(void* const* d_in, const int* in_sizes, int n_in,
                              void* d_out, int out_size) {
    const float* sc = (const float*)d_in[0];
    int T = in_sizes[0] / (NB * CC);
    int Tf = (int)(((long long)T * 3) / 5);   // backward step is heavier on smem
    if (Tf < 1) Tf = 1;
    if (Tf > T - 1) Tf = T - 1;

    cudaFuncSetAttribute(crf_scan, cudaFuncAttributeMaxDynamicSharedMemorySize, SMEM_B);
    crf_scan<<<dim3(NB, 2), TPB, SMEM_B>>>(sc, T, Tf);
    crf_combine<<<NB, TPB>>>((float*)d_out);
}

// round 3
// speedup vs baseline: 1.0410x; 1.0410x over previous
#include <cuda_runtime.h>
#include <cuda_bf16.h>
#include <cstdint>
#include <cstddef>

// ---------------------------------------------------------------------------
// CTC-CRF logZ (bonito): S=1024, NZ=5, N=32, T=2000.
// Forward (t<Tf) and backward (t>=Tf) scans in parallel, grid (32,2);
// logZ = log( alpha_mid . beta_mid ). Exp2-domain, renorm every 8 steps.
// R3: bf16 backward exchange planes, weight (EX2) pipelining one step ahead,
// 6-stage cp.async, one barrier per step, rebalanced split.
// ---------------------------------------------------------------------------

#define NB   32
#define SS   1024
#define CC   5120
#define TPB  256
#define L2E  1.44269504088896f
#define LN2  0.69314718055995f
#define STAGES 6
#define DIST   5

// smem floats: [0, 6*5120) score stages; [30720, 34816) work (fw: alpha 2x1024;
// bw: 2 buf x 4 planes x 1024 bf16 = 16KB); [34816, 34824) reduction.
#define WOFF   30720
#define REDOFF (WOFF + 4096)
#define SMEM_BYTES ((REDOFF + 8) * 4)

__device__ __align__(16) float g_mid_a[NB][SS];
__device__ __align__(16) float g_mid_b[NB][SS];
__device__ float g_off[2][NB];

__device__ __forceinline__ float ex2f_(float x) {
    float r; asm("ex2.approx.f32 %0,%1;" : "=f"(r) : "f"(x)); return r;
}
__device__ __forceinline__ float lg2f_(float x) {
    float r; asm("lg2.approx.f32 %0,%1;" : "=f"(r) : "f"(x)); return r;
}
__device__ __forceinline__ float rcpf_(float x) {
    float r; asm("rcp.approx.f32 %0,%1;" : "=f"(r) : "f"(x)); return r;
}
__device__ __forceinline__ uint32_t pack_bf2(float a, float b) {
    __nv_bfloat162 h = __floats2bfloat162_rn(a, b);
    return *reinterpret_cast<uint32_t*>(&h);
}
__device__ __forceinline__ float2 unpack_bf2(uint32_t u) {
    __nv_bfloat162 h = *reinterpret_cast<__nv_bfloat162*>(&u);
    return __bfloat1622float2(h);
}

__device__ __forceinline__ void cp_slab(const float* g, float* s, int tid) {
    uint32_t dst = (uint32_t)__cvta_generic_to_shared(s) + (uint32_t)tid * 16u;
    const char* src = (const char*)g + (size_t)tid * 16;
#pragma unroll
    for (int k = 0; k < 5; k++)
        asm volatile("cp.async.cg.shared.global [%0],[%1],16;"
                     :: "r"(dst + (uint32_t)k * 4096u), "l"(src + (size_t)k * 4096)
                     : "memory");
}
__device__ __forceinline__ void cp_commit() {
    asm volatile("cp.async.commit_group;" ::: "memory");
}
__device__ __forceinline__ void cp_wait3() {
    asm volatile("cp.async.wait_group 3;" ::: "memory");
}
__device__ __forceinline__ float wmaxf_(float m) {
#pragma unroll
    for (int o = 16; o; o >>= 1)
        m = fmaxf(m, __shfl_xor_sync(0xffffffffu, m, o));
    return m;
}
__device__ __forceinline__ float redmax_(const volatile float* red) {
    float mv = red[0];
#pragma unroll
    for (int k = 1; k < 8; k++) mv = fmaxf(mv, red[k]);
    return mv;
}

// Load 20 weights = exp2(score * log2e) for one slab into register array W.
#define LOADW(W, sbase) do {                                                   \
    const float4* sp_ = (const float4*)(sbase) + 5 * tid;                      \
    float4 q0_ = sp_[0], q1_ = sp_[1], q2_ = sp_[2], q3_ = sp_[3], q4_ = sp_[4];\
    W[0]=ex2f_(q0_.x*L2E);  W[1]=ex2f_(q0_.y*L2E);  W[2]=ex2f_(q0_.z*L2E);  W[3]=ex2f_(q0_.w*L2E); \
    W[4]=ex2f_(q1_.x*L2E);  W[5]=ex2f_(q1_.y*L2E);  W[6]=ex2f_(q1_.z*L2E);  W[7]=ex2f_(q1_.w*L2E); \
    W[8]=ex2f_(q2_.x*L2E);  W[9]=ex2f_(q2_.y*L2E);  W[10]=ex2f_(q2_.z*L2E); W[11]=ex2f_(q2_.w*L2E);\
    W[12]=ex2f_(q3_.x*L2E); W[13]=ex2f_(q3_.y*L2E); W[14]=ex2f_(q3_.z*L2E); W[15]=ex2f_(q3_.w*L2E);\
    W[16]=ex2f_(q4_.x*L2E); W[17]=ex2f_(q4_.y*L2E); W[18]=ex2f_(q4_.z*L2E); W[19]=ex2f_(q4_.w*L2E);\
} while (0)

#define ISSUE(IDX) do {                                                        \
    int j_ = (IDX);                                                            \
    if (j_ < steps) {                                                          \
        int t_ = dir ? (T - 1 - j_) : j_;                                      \
        cp_slab(sc + ((size_t)t_ * NB + n) * CC, sm + (j_ % STAGES) * CC, tid);\
    }                                                                          \
    cp_commit();                                                               \
} while (0)

// ---- forward step: state s=4*tid+m; preds: s (stay), tid+256r (moves) ----
#define FWSTEP(I, WC, WN) do {                                                 \
    int i_ = (I);                                                              \
    ISSUE(i_ + DIST);                                                          \
    cp_wait3();                                                                \
    const float* ac_ = al + (i_ & 1) * SS;                                     \
    float g0_ = ac_[tid], g1_ = ac_[tid+256], g2_ = ac_[tid+512], g3_ = ac_[tid+768]; \
    if ((i_ & 7) == 0 && i_) {                                                 \
        float mv_ = redmax_(red); float s_ = rcpf_(mv_); off += lg2f_(mv_);    \
        a0*=s_; a1*=s_; a2*=s_; a3*=s_; g0_*=s_; g1_*=s_; g2_*=s_; g3_*=s_;   \
    }                                                                          \
    float n0_ = fmaf(WC[1],  g0_, WC[0]  * a0);                                \
    n0_ = fmaf(WC[2],  g1_, n0_); n0_ = fmaf(WC[3],  g2_, n0_); n0_ = fmaf(WC[4],  g3_, n0_); \
    float n1_ = fmaf(WC[6],  g0_, WC[5]  * a1);                                \
    n1_ = fmaf(WC[7],  g1_, n1_); n1_ = fmaf(WC[8],  g2_, n1_); n1_ = fmaf(WC[9],  g3_, n1_); \
    float n2_ = fmaf(WC[11], g0_, WC[10] * a2);                                \
    n2_ = fmaf(WC[12], g1_, n2_); n2_ = fmaf(WC[13], g2_, n2_); n2_ = fmaf(WC[14], g3_, n2_); \
    float n3_ = fmaf(WC[16], g0_, WC[15] * a3);                                \
    n3_ = fmaf(WC[17], g1_, n3_); n3_ = fmaf(WC[18], g2_, n3_); n3_ = fmaf(WC[19], g3_, n3_); \
    a0 = n0_; a1 = n1_; a2 = n2_; a3 = n3_;                                    \
    ((float4*)(al + ((i_ + 1) & 1) * SS))[tid] = make_float4(n0_, n1_, n2_, n3_); \
    if ((i_ & 7) == 7) {                                                       \
        float m_ = wmaxf_(fmaxf(fmaxf(n0_, n1_), fmaxf(n2_, n3_)));            \
        if (lane == 0) red[wid] = m_;                                          \
    }                                                                          \
    if (i_ + 1 < steps) { LOADW(WN, sm + ((i_ + 1) % STAGES) * CC); }          \
    __syncthreads();                                                           \
} while (0)

// ---- backward step: owner of s computes c_z = w_z*b_s, scatters to bf16
// planes; state j gathers 4 contiguous entries of plane (j>>8). ----
#define BWSTEP(I, WC, WN) do {                                                 \
    int i_ = (I);                                                              \
    ISSUE(i_ + DIST);                                                          \
    cp_wait3();                                                                \
    char* pb_ = wk + (i_ & 1) * 8192;                                          \
    *(uint2*)(pb_ + 0*2048 + off_sc) = make_uint2(pack_bf2(WC[1]*b0,  WC[6]*b1),  pack_bf2(WC[11]*b2, WC[16]*b3)); \
    *(uint2*)(pb_ + 1*2048 + off_sc) = make_uint2(pack_bf2(WC[2]*b0,  WC[7]*b1),  pack_bf2(WC[12]*b2, WC[17]*b3)); \
    *(uint2*)(pb_ + 2*2048 + off_sc) = make_uint2(pack_bf2(WC[3]*b0,  WC[8]*b1),  pack_bf2(WC[13]*b2, WC[18]*b3)); \
    *(uint2*)(pb_ + 3*2048 + off_sc) = make_uint2(pack_bf2(WC[4]*b0,  WC[9]*b1),  pack_bf2(WC[14]*b2, WC[19]*b3)); \
    float st0_ = WC[0]*b0, st1_ = WC[5]*b1, st2_ = WC[10]*b2, st3_ = WC[15]*b3; \
    if (i_ + 1 < steps) { LOADW(WN, sm + ((i_ + 1) % STAGES) * CC); }          \
    __syncthreads();                                                           \
    float psc_ = 1.0f;                                                         \
    if ((i_ & 7) == 0 && i_) {                                                 \
        float mv_ = redmax_(red); psc_ = rcpf_(mv_); off += lg2f_(mv_);        \
    }                                                                          \
    const char* gb_ = pb_ + zj * 2048;                                         \
    uint4 A_ = *(const uint4*)(gb_ + ga0);                                     \
    uint4 B_ = *(const uint4*)(gb_ + ga1);                                     \
    float2 p_;                                                                 \
    p_ = unpack_bf2(A_.x); float s0_ = p_.x + p_.y;                            \
    p_ = unpack_bf2(A_.y); s0_ += p_.x + p_.y;                                 \
    p_ = unpack_bf2(A_.z); float s1_ = p_.x + p_.y;                            \
    p_ = unpack_bf2(A_.w); s1_ += p_.x + p_.y;                                 \
    p_ = unpack_bf2(B_.x); float s2_ = p_.x + p_.y;                            \
    p_ = unpack_bf2(B_.y); s2_ += p_.x + p_.y;                                 \
    p_ = unpack_bf2(B_.z); float s3_ = p_.x + p_.y;                            \
    p_ = unpack_bf2(B_.w); s3_ += p_.x + p_.y;                                 \
    b0 = psc_ * (st0_ + s0_); b1 = psc_ * (st1_ + s1_);                        \
    b2 = psc_ * (st2_ + s2_); b3 = psc_ * (st3_ + s3_);                        \
    if ((i_ & 7) == 7) {                                                       \
        float m_ = wmaxf_(fmaxf(fmaxf(b0, b1), fmaxf(b2, b3)));                \
        if (lane == 0) red[wid] = m_;                                          \
    }                                                                          \
} while (0)

__global__ void __launch_bounds__(TPB, 1)
crf_scan(const float* __restrict__ sc, int T, int Tf) {
    extern __shared__ float sm[];
    const int tid  = threadIdx.x;
    const int n    = blockIdx.x;
    const int dir  = blockIdx.y;
    const int wid  = tid >> 5;
    const int lane = tid & 31;
    volatile float* red = sm + REDOFF;
    const int steps = dir ? (T - Tf) : Tf;

    // prologue: slabs 0..4 in flight; guarantee slabs 0,1 resident block-wide
#pragma unroll
    for (int p = 0; p < DIST; p++) ISSUE(p);
    cp_wait3();
    __syncthreads();

    float wA[20], wB[20];
    LOADW(wA, sm + 0 * CC);
    float off = 0.0f;

    if (dir == 0) {
        float* al = sm + WOFF;
        float a0 = 1.f, a1 = 1.f, a2 = 1.f, a3 = 1.f;
        ((float4*)al)[tid] = make_float4(1.f, 1.f, 1.f, 1.f);
        __syncthreads();

        int i = 0;
        for (; i + 1 < steps; i += 2) { FWSTEP(i, wA, wB); FWSTEP(i + 1, wB, wA); }
        if (i < steps) { FWSTEP(i, wA, wB); }

        float m = wmaxf_(fmaxf(fmaxf(a0, a1), fmaxf(a2, a3)));
        if (lane == 0) red[wid] = m;
        __syncthreads();
        float mv = redmax_(red);
        float s = rcpf_(mv);
        off += lg2f_(mv);
        ((float4*)g_mid_a[n])[tid] = make_float4(a0 * s, a1 * s, a2 * s, a3 * s);
        if (tid == 0) g_off[0][n] = off;
    } else {
        char* wk = (char*)(sm + WOFF);
        float b0 = 1.f, b1 = 1.f, b2 = 1.f, b3 = 1.f;
        // scatter: entries 4t..4t+3 = chunk c=t>>1 (half t&1), chunk swizzle
        // f(c) = c ^ ((c>>3)&7); gather: chunks 2u, 2u+1 with u = t&63.
        const int c_  = tid >> 1;
        const int off_sc = 16 * (c_ ^ ((c_ >> 3) & 7)) + 8 * (tid & 1);
        const int u_  = tid & 63;
        const int zj  = tid >> 6;
        const int ga0 = 16 * ((2 * u_)     ^ (((2 * u_)     >> 3) & 7));
        const int ga1 = 16 * ((2 * u_ + 1) ^ (((2 * u_ + 1) >> 3) & 7));

        int i = 0;
        for (; i + 1 < steps; i += 2) { BWSTEP(i, wA, wB); BWSTEP(i + 1, wB, wA); }
        if (i < steps) { BWSTEP(i, wA, wB); }

        float m = wmaxf_(fmaxf(fmaxf(b0, b1), fmaxf(b2, b3)));
        if (lane == 0) red[wid] = m;
        __syncthreads();
        float mv = redmax_(red);
        float s = rcpf_(mv);
        off += lg2f_(mv);
        ((float4*)g_mid_b[n])[tid] = make_float4(b0 * s, b1 * s, b2 * s, b3 * s);
        if (tid == 0) g_off[1][n] = off;
    }
}

__global__ void __launch_bounds__(TPB)
crf_combine(float* __restrict__ out) {
    __shared__ float par[8];
    const int n = blockIdx.x, tid = threadIdx.x;
    float4 a = ((const float4*)g_mid_a[n])[tid];
    float4 b = ((const float4*)g_mid_b[n])[tid];
    float s = a.x * b.x + a.y * b.y + a.z * b.z + a.w * b.w;
#pragma unroll
    for (int o = 16; o; o >>= 1) s += __shfl_xor_sync(0xffffffffu, s, o);
    if ((tid & 31) == 0) par[tid >> 5] = s;
    __syncthreads();
    if (tid == 0) {
        float t = par[0];
#pragma unroll
        for (int k = 1; k < 8; k++) t += par[k];
        out[n] = LN2 * (g_off[0][n] + g_off[1][n] + lg2f_(t));
    }
}

extern "C" void kernel_launch(void* const* d_in, const int* in_sizes, int n_in,
                              void* d_out, int out_size) {
    const float* sc = (const float*)d_in[0];
    int T = in_sizes[0] / (NB * CC);
    int Tf = (int)(((long long)T * 538) / 1000);   // fw floor 384 vs bw floor 448
    if (Tf < 1) Tf = 1;
    if (Tf > T - 1) Tf = T - 1;

    cudaFuncSetAttribute(crf_scan, cudaFuncAttributeMaxDynamicSharedMemorySize, SMEM_BYTES);
    crf_scan<<<dim3(NB, 2), TPB, SMEM_BYTES>>>(sc, T, Tf);
    crf_combine<<<NB, TPB>>>((float*)d_out);
}

// round 4
// speedup vs baseline: 1.0468x; 1.0055x over previous
#include <cuda_runtime.h>
#include <cuda_bf16.h>
#include <cstdint>
#include <cstddef>

// ---------------------------------------------------------------------------
// CTC-CRF logZ (bonito): S=1024, NZ=5, N=32, T=2000.
// Forward (t<Tf) and backward (t>=Tf) scans in parallel, grid (32,2);
// logZ = log( alpha_mid . beta_mid ). Exp2-domain, renorm every 8 steps.
// R4: 9-stage / wait_group-6 cp.async pipeline (130 KB in flight per SM) to
// lift the per-SM DRAM delivery cap; profiling pad kernels so ncu -s5 -c1
// lands on crf_scan.
// ---------------------------------------------------------------------------

#define NB   32
#define SS   1024
#define CC   5120
#define TPB  256
#define L2E  1.44269504088896f
#define LN2  0.69314718055995f
#define STAGES 9
#define DIST   8

// smem floats: [0, 9*5120) score stages; [46080, 50176) work (fw: alpha
// 2x1024 f32; bw: 2 x 4 planes x 1024 bf16); [50176, +8) reduction.
#define WOFF   46080
#define REDOFF (WOFF + 4096)
#define SMEM_BYTES ((REDOFF + 8) * 4)

__device__ __align__(16) float g_mid_a[NB][SS];
__device__ __align__(16) float g_mid_b[NB][SS];
__device__ float g_off[2][NB];

__device__ __forceinline__ float ex2f_(float x) {
    float r; asm("ex2.approx.f32 %0,%1;" : "=f"(r) : "f"(x)); return r;
}
__device__ __forceinline__ float lg2f_(float x) {
    float r; asm("lg2.approx.f32 %0,%1;" : "=f"(r) : "f"(x)); return r;
}
__device__ __forceinline__ float rcpf_(float x) {
    float r; asm("rcp.approx.f32 %0,%1;" : "=f"(r) : "f"(x)); return r;
}
__device__ __forceinline__ uint32_t pack_bf2(float a, float b) {
    __nv_bfloat162 h = __floats2bfloat162_rn(a, b);
    return *reinterpret_cast<uint32_t*>(&h);
}
__device__ __forceinline__ float2 unpack_bf2(uint32_t u) {
    __nv_bfloat162 h = *reinterpret_cast<__nv_bfloat162*>(&u);
    return __bfloat1622float2(h);
}

__device__ __forceinline__ void cp_slab(const float* g, float* s, int tid) {
    uint32_t dst = (uint32_t)__cvta_generic_to_shared(s) + (uint32_t)tid * 16u;
    const char* src = (const char*)g + (size_t)tid * 16;
#pragma unroll
    for (int k = 0; k < 5; k++)
        asm volatile("cp.async.cg.shared.global [%0],[%1],16;"
                     :: "r"(dst + (uint32_t)k * 4096u), "l"(src + (size_t)k * 4096)
                     : "memory");
}
__device__ __forceinline__ void cp_commit() {
    asm volatile("cp.async.commit_group;" ::: "memory");
}
__device__ __forceinline__ void cp_wait6() {
    asm volatile("cp.async.wait_group 6;" ::: "memory");
}
__device__ __forceinline__ float wmaxf_(float m) {
#pragma unroll
    for (int o = 16; o; o >>= 1)
        m = fmaxf(m, __shfl_xor_sync(0xffffffffu, m, o));
    return m;
}
__device__ __forceinline__ float redmax_(const volatile float* red) {
    float mv = red[0];
#pragma unroll
    for (int k = 1; k < 8; k++) mv = fmaxf(mv, red[k]);
    return mv;
}

#define LOADW(W, sbase) do {                                                   \
    const float4* sp_ = (const float4*)(sbase) + 5 * tid;                      \
    float4 q0_ = sp_[0], q1_ = sp_[1], q2_ = sp_[2], q3_ = sp_[3], q4_ = sp_[4];\
    W[0]=ex2f_(q0_.x*L2E);  W[1]=ex2f_(q0_.y*L2E);  W[2]=ex2f_(q0_.z*L2E);  W[3]=ex2f_(q0_.w*L2E); \
    W[4]=ex2f_(q1_.x*L2E);  W[5]=ex2f_(q1_.y*L2E);  W[6]=ex2f_(q1_.z*L2E);  W[7]=ex2f_(q1_.w*L2E); \
    W[8]=ex2f_(q2_.x*L2E);  W[9]=ex2f_(q2_.y*L2E);  W[10]=ex2f_(q2_.z*L2E); W[11]=ex2f_(q2_.w*L2E);\
    W[12]=ex2f_(q3_.x*L2E); W[13]=ex2f_(q3_.y*L2E); W[14]=ex2f_(q3_.z*L2E); W[15]=ex2f_(q3_.w*L2E);\
    W[16]=ex2f_(q4_.x*L2E); W[17]=ex2f_(q4_.y*L2E); W[18]=ex2f_(q4_.z*L2E); W[19]=ex2f_(q4_.w*L2E);\
} while (0)

#define ISSUE(IDX) do {                                                        \
    int j_ = (IDX);                                                            \
    if (j_ < steps) {                                                          \
        int t_ = dir ? (T - 1 - j_) : j_;                                      \
        cp_slab(sc + ((size_t)t_ * NB + n) * CC, sm + (j_ % STAGES) * CC, tid);\
    }                                                                          \
    cp_commit();                                                               \
} while (0)

// ---- forward step: state s=4*tid+m; preds: s (stay), tid+256r (moves) ----
#define FWSTEP(I, WC, WN) do {                                                 \
    int i_ = (I);                                                              \
    ISSUE(i_ + DIST);                                                          \
    cp_wait6();                                                                \
    const float* ac_ = al + (i_ & 1) * SS;                                     \
    float g0_ = ac_[tid], g1_ = ac_[tid+256], g2_ = ac_[tid+512], g3_ = ac_[tid+768]; \
    if ((i_ & 7) == 0 && i_) {                                                 \
        float mv_ = redmax_(red); float s_ = rcpf_(mv_); off += lg2f_(mv_);    \
        a0*=s_; a1*=s_; a2*=s_; a3*=s_; g0_*=s_; g1_*=s_; g2_*=s_; g3_*=s_;   \
    }                                                                          \
    float n0_ = fmaf(WC[1],  g0_, WC[0]  * a0);                                \
    n0_ = fmaf(WC[2],  g1_, n0_); n0_ = fmaf(WC[3],  g2_, n0_); n0_ = fmaf(WC[4],  g3_, n0_); \
    float n1_ = fmaf(WC[6],  g0_, WC[5]  * a1);                                \
    n1_ = fmaf(WC[7],  g1_, n1_); n1_ = fmaf(WC[8],  g2_, n1_); n1_ = fmaf(WC[9],  g3_, n1_); \
    float n2_ = fmaf(WC[11], g0_, WC[10] * a2);                                \
    n2_ = fmaf(WC[12], g1_, n2_); n2_ = fmaf(WC[13], g2_, n2_); n2_ = fmaf(WC[14], g3_, n2_); \
    float n3_ = fmaf(WC[16], g0_, WC[15] * a3);                                \
    n3_ = fmaf(WC[17], g1_, n3_); n3_ = fmaf(WC[18], g2_, n3_); n3_ = fmaf(WC[19], g3_, n3_); \
    a0 = n0_; a1 = n1_; a2 = n2_; a3 = n3_;                                    \
    ((float4*)(al + ((i_ + 1) & 1) * SS))[tid] = make_float4(n0_, n1_, n2_, n3_); \
    if ((i_ & 7) == 7) {                                                       \
        float m_ = wmaxf_(fmaxf(fmaxf(n0_, n1_), fmaxf(n2_, n3_)));            \
        if (lane == 0) red[wid] = m_;                                          \
    }                                                                          \
    if (i_ + 1 < steps) { LOADW(WN, sm + ((i_ + 1) % STAGES) * CC); }          \
    __syncthreads();                                                           \
} while (0)

// ---- backward step: owner of s computes c_z = w_z*b_s, scatters to bf16
// planes; state j gathers 4 contiguous entries of plane (j>>8). ----
#define BWSTEP(I, WC, WN) do {                                                 \
    int i_ = (I);                                                              \
    ISSUE(i_ + DIST);                                                          \
    cp_wait6();                                                                \
    char* pb_ = wk + (i_ & 1) * 8192;                                          \
    *(uint2*)(pb_ + 0*2048 + off_sc) = make_uint2(pack_bf2(WC[1]*b0,  WC[6]*b1),  pack_bf2(WC[11]*b2, WC[16]*b3)); \
    *(uint2*)(pb_ + 1*2048 + off_sc) = make_uint2(pack_bf2(WC[2]*b0,  WC[7]*b1),  pack_bf2(WC[12]*b2, WC[17]*b3)); \
    *(uint2*)(pb_ + 2*2048 + off_sc) = make_uint2(pack_bf2(WC[3]*b0,  WC[8]*b1),  pack_bf2(WC[13]*b2, WC[18]*b3)); \
    *(uint2*)(pb_ + 3*2048 + off_sc) = make_uint2(pack_bf2(WC[4]*b0,  WC[9]*b1),  pack_bf2(WC[14]*b2, WC[19]*b3)); \
    float st0_ = WC[0]*b0, st1_ = WC[5]*b1, st2_ = WC[10]*b2, st3_ = WC[15]*b3; \
    if (i_ + 1 < steps) { LOADW(WN, sm + ((i_ + 1) % STAGES) * CC); }          \
    __syncthreads();                                                           \
    float psc_ = 1.0f;                                                         \
    if ((i_ & 7) == 0 && i_) {                                                 \
        float mv_ = redmax_(red); psc_ = rcpf_(mv_); off += lg2f_(mv_);        \
    }                                                                          \
    const char* gb_ = pb_ + zj * 2048;                                         \
    uint4 A_ = *(const uint4*)(gb_ + ga0);                                     \
    uint4 B_ = *(const uint4*)(gb_ + ga1);                                     \
    float2 p_;                                                                 \
    p_ = unpack_bf2(A_.x); float s0_ = p_.x + p_.y;                            \
    p_ = unpack_bf2(A_.y); s0_ += p_.x + p_.y;                                 \
    p_ = unpack_bf2(A_.z); float s1_ = p_.x + p_.y;                            \
    p_ = unpack_bf2(A_.w); s1_ += p_.x + p_.y;                                 \
    p_ = unpack_bf2(B_.x); float s2_ = p_.x + p_.y;                            \
    p_ = unpack_bf2(B_.y); s2_ += p_.x + p_.y;                                 \
    p_ = unpack_bf2(B_.z); float s3_ = p_.x + p_.y;                            \
    p_ = unpack_bf2(B_.w); s3_ += p_.x + p_.y;                                 \
    b0 = psc_ * (st0_ + s0_); b1 = psc_ * (st1_ + s1_);                        \
    b2 = psc_ * (st2_ + s2_); b3 = psc_ * (st3_ + s3_);                        \
    if ((i_ & 7) == 7) {                                                       \
        float m_ = wmaxf_(fmaxf(fmaxf(b0, b1), fmaxf(b2, b3)));                \
        if (lane == 0) red[wid] = m_;                                          \
    }                                                                          \
} while (0)

__global__ void __launch_bounds__(TPB, 1)
crf_scan(const float* __restrict__ sc, int T, int Tf) {
    extern __shared__ float sm[];
    const int tid  = threadIdx.x;
    const int n    = blockIdx.x;
    const int dir  = blockIdx.y;
    const int wid  = tid >> 5;
    const int lane = tid & 31;
    volatile float* red = sm + REDOFF;
    const int steps = dir ? (T - Tf) : Tf;

    // prologue: slabs 0..DIST-1 in flight; slab 0 resident block-wide
#pragma unroll
    for (int p = 0; p < DIST; p++) ISSUE(p);
    cp_wait6();
    __syncthreads();

    float wA[20], wB[20];
    LOADW(wA, sm + 0 * CC);
    float off = 0.0f;

    if (dir == 0) {
        float* al = sm + WOFF;
        float a0 = 1.f, a1 = 1.f, a2 = 1.f, a3 = 1.f;
        ((float4*)al)[tid] = make_float4(1.f, 1.f, 1.f, 1.f);
        __syncthreads();

        int i = 0;
        for (; i + 1 < steps; i += 2) { FWSTEP(i, wA, wB); FWSTEP(i + 1, wB, wA); }
        if (i < steps) { FWSTEP(i, wA, wB); }

        float m = wmaxf_(fmaxf(fmaxf(a0, a1), fmaxf(a2, a3)));
        if (lane == 0) red[wid] = m;
        __syncthreads();
        float mv = redmax_(red);
        float s = rcpf_(mv);
        off += lg2f_(mv);
        ((float4*)g_mid_a[n])[tid] = make_float4(a0 * s, a1 * s, a2 * s, a3 * s);
        if (tid == 0) g_off[0][n] = off;
    } else {
        char* wk = (char*)(sm + WOFF);
        float b0 = 1.f, b1 = 1.f, b2 = 1.f, b3 = 1.f;
        const int c_  = tid >> 1;
        const int off_sc = 16 * (c_ ^ ((c_ >> 3) & 7)) + 8 * (tid & 1);
        const int u_  = tid & 63;
        const int zj  = tid >> 6;
        const int ga0 = 16 * ((2 * u_)     ^ (((2 * u_)     >> 3) & 7));
        const int ga1 = 16 * ((2 * u_ + 1) ^ (((2 * u_ + 1) >> 3) & 7));

        int i = 0;
        for (; i + 1 < steps; i += 2) { BWSTEP(i, wA, wB); BWSTEP(i + 1, wB, wA); }
        if (i < steps) { BWSTEP(i, wA, wB); }

        float m = wmaxf_(fmaxf(fmaxf(b0, b1), fmaxf(b2, b3)));
        if (lane == 0) red[wid] = m;
        __syncthreads();
        float mv = redmax_(red);
        float s = rcpf_(mv);
        off += lg2f_(mv);
        ((float4*)g_mid_b[n])[tid] = make_float4(b0 * s, b1 * s, b2 * s, b3 * s);
        if (tid == 0) g_off[1][n] = off;
    }
}

__global__ void __launch_bounds__(TPB)
crf_combine(float* __restrict__ out) {
    __shared__ float par[8];
    const int n = blockIdx.x, tid = threadIdx.x;
    float4 a = ((const float4*)g_mid_a[n])[tid];
    float4 b = ((const float4*)g_mid_b[n])[tid];
    float s = a.x * b.x + a.y * b.y + a.z * b.z + a.w * b.w;
#pragma unroll
    for (int o = 16; o; o >>= 1) s += __shfl_xor_sync(0xffffffffu, s, o);
    if ((tid & 31) == 0) par[tid >> 5] = s;
    __syncthreads();
    if (tid == 0) {
        float t = par[0];
#pragma unroll
        for (int k = 1; k < 8; k++) t += par[k];
        out[n] = LN2 * (g_off[0][n] + g_off[1][n] + lg2f_(t));
    }
}

// Profiling pad: with launch order (pad, scan, combine, pad) the 6th process
// launch is crf_scan, which is what ncu -s 5 -c 1 captures.
__global__ void prof_pad() {}

extern "C" void kernel_launch(void* const* d_in, const int* in_sizes, int n_in,
                              void* d_out, int out_size) {
    const float* sc = (const float*)d_in[0];
    int T = in_sizes[0] / (NB * CC);
    int Tf = (int)(((long long)T * 538) / 1000);
    if (Tf < 1) Tf = 1;
    if (Tf > T - 1) Tf = T - 1;

    cudaFuncSetAttribute(crf_scan, cudaFuncAttributeMaxDynamicSharedMemorySize, SMEM_BYTES);
    prof_pad<<<1, 32>>>();
    crf_scan<<<dim3(NB, 2), TPB, SMEM_BYTES>>>(sc, T, Tf);
    crf_combine<<<NB, TPB>>>((float*)d_out);
    prof_pad<<<1, 32>>>();
}